// round 3
// baseline (speedup 1.0000x reference)
#include <cuda_runtime.h>
#include <math.h>

// QuantumLayer: 4-qubit circuit, closed-form with phase folding.
//   z_q = kc_q*cos(x_q) + ks_q*sin(x_q) = R_q * cos(x_q - delta_q)
//     kc = cos(theta), ks = -cos(phi)*sin(theta)
//   out0 = z1 z2 z3 = C0 * c1 c2 c3      C0 = R1 R2 R3
//   out1 = z0 z1    = C1 * c0 c1         C1 = R0 R1
//   out2 = z0 z1 z2 = C2 * c0 c1 c2      C2 = R0 R1 R2
//   out3 = z0..z3   = C3 * c0 c1 c2 c3   C3 = R0 R1 R2 R3
// where c_q = cos(x_q - delta_q). Output layout: [NQ, B] float32.

#define SAMP 4
#define TPB  256

__global__ __launch_bounds__(TPB)
void quantum_layer_kernel(const float* __restrict__ x,
                          const float* __restrict__ w,
                          float* __restrict__ out,
                          int B) {
    __shared__ float sD[4];   // delta_q
    __shared__ float sR[4];   // R_q
    if (threadIdx.x < 4) {
        int q = threadIdx.x;
        float phi   = w[q * 3 + 0];
        float theta = w[q * 3 + 1];
        float st, ct;
        __sincosf(theta, &st, &ct);
        float kc = ct;
        float ks = -__cosf(phi) * st;
        sR[q] = sqrtf(kc * kc + ks * ks);
        sD[q] = atan2f(ks, kc);            // accurate path, runs on 4 threads once
    }
    __syncthreads();

    const float d0 = sD[0], d1 = sD[1], d2 = sD[2], d3 = sD[3];
    const float R0 = sR[0], R1 = sR[1], R2 = sR[2], R3 = sR[3];
    const float C1 = R0 * R1;
    const float C2 = C1 * R2;
    const float C3 = C2 * R3;
    const float C0 = R1 * R2 * R3;

    const float4* __restrict__ xv4 = reinterpret_cast<const float4*>(x);

    int tile = blockIdx.x * (TPB * SAMP);
    int i0   = tile + threadIdx.x;

    // Front-batch all loads (coalesced, MLP=4).
    float4 xv[SAMP];
#pragma unroll
    for (int j = 0; j < SAMP; ++j) {
        int i = i0 + j * TPB;
        if (i < B) xv[j] = xv4[i];
    }

    float r0[SAMP], r1[SAMP], r2[SAMP], r3[SAMP];
#pragma unroll
    for (int j = 0; j < SAMP; ++j) {
        float c0 = __cosf(xv[j].x - d0);
        float c1 = __cosf(xv[j].y - d1);
        float c2 = __cosf(xv[j].z - d2);
        float c3 = __cosf(xv[j].w - d3);

        float a = c0 * c1;       // c0 c1
        float b = c2 * c3;       // c2 c3
        r0[j] = C0 * (c1 * b);   // z1 z2 z3
        r1[j] = C1 * a;          // z0 z1
        r2[j] = C2 * (a * c2);   // z0 z1 z2
        r3[j] = C3 * (a * b);    // z0 z1 z2 z3
    }

    float* __restrict__ o0 = out;
    float* __restrict__ o1 = out + (size_t)B;
    float* __restrict__ o2 = out + 2 * (size_t)B;
    float* __restrict__ o3 = out + 3 * (size_t)B;

#pragma unroll
    for (int j = 0; j < SAMP; ++j) {
        int i = i0 + j * TPB;
        if (i < B) {
            o0[i] = r0[j];
            o1[i] = r1[j];
            o2[i] = r2[j];
            o3[i] = r3[j];
        }
    }
}

extern "C" void kernel_launch(void* const* d_in, const int* in_sizes, int n_in,
                              void* d_out, int out_size) {
    const float* x = (const float*)d_in[0];   // inputs  [B, 4] float32
    const float* w = (const float*)d_in[1];   // weights [1, 4, 3] float32
    float* out = (float*)d_out;               // [4, B] float32

    int B = in_sizes[0] / 4;                  // 1<<20
    int samplesPerBlock = TPB * SAMP;
    int blocks = (B + samplesPerBlock - 1) / samplesPerBlock;

    quantum_layer_kernel<<<blocks, TPB>>>(x, w, out, B);
}